// round 2
// baseline (speedup 1.0000x reference)
#include <cuda_runtime.h>

#define BB 8
#define SS 2048
#define DD 768
#define NSP 512
#define MAXW 30
#define HH 100
#define M_TOTAL (BB*NSP)   /* 4096 */

__device__ float g_logits[BB*SS];
__device__ float g_att[(size_t)M_TOTAL*DD];
__device__ float g_part[2*(size_t)M_TOTAL*HH];

// ---------------- Kernel 1: attention logits over full sequence ----------------
// grid = (B*S)/8 blocks, 256 threads (8 warps, 1 position per warp)
__global__ void k_logits(const float* __restrict__ seq,
                         const float* __restrict__ att_w,
                         const float* __restrict__ att_b) {
    __shared__ float sw[DD];
    int tid = threadIdx.x;
    for (int i = tid; i < DD; i += blockDim.x) sw[i] = att_w[i];
    __syncthreads();
    int warp = tid >> 5, lane = tid & 31;
    int p = blockIdx.x * 8 + warp;                    // 0..B*S-1
    const float4* s4 = (const float4*)(seq + (size_t)p * DD);
    const float4* w4 = (const float4*)sw;
    float sum = 0.f;
#pragma unroll
    for (int j = 0; j < 6; j++) {
        float4 a = s4[lane + 32 * j];
        float4 w = w4[lane + 32 * j];
        sum += a.x * w.x + a.y * w.y + a.z * w.z + a.w * w.w;
    }
#pragma unroll
    for (int o = 16; o > 0; o >>= 1) sum += __shfl_xor_sync(0xffffffffu, sum, o);
    if (lane == 0) g_logits[p] = sum + att_b[0];
}

// ---------------- Kernel 2: per-span softmax + weighted sum of token rows ------
// grid = 4096 blocks (one per span), 192 threads (one float4 column of D each)
// NOTE: span_indices is int32 (JAX x64 disabled downcasts the int64 astype).
__global__ void k_span(const float* __restrict__ seq,
                       const int* __restrict__ spans,
                       const int* __restrict__ mask) {
    __shared__ float s_attn[MAXW];
    __shared__ int   s_start, s_cnt;
    int sp  = blockIdx.x;
    int b   = sp >> 9;
    int tid = threadIdx.x;

    if (tid < 32) {
        int start = spans[sp * 2];
        int cnt   = spans[sp * 2 + 1] - start;        // inclusive width, 1..30
        float lg = (tid < cnt) ? g_logits[b * SS + start + tid] : -1e30f;
        float mx = lg;
#pragma unroll
        for (int o = 16; o > 0; o >>= 1) mx = fmaxf(mx, __shfl_xor_sync(0xffffffffu, mx, o));
        float ex = (tid < cnt) ? expf(lg - mx) : 0.f;
        float sm = ex;
#pragma unroll
        for (int o = 16; o > 0; o >>= 1) sm += __shfl_xor_sync(0xffffffffu, sm, o);
        float mk = (float)mask[sp];
        if (tid < MAXW) s_attn[tid] = ex / sm * mk;
        if (tid == 0) { s_start = start; s_cnt = cnt; }
    }
    __syncthreads();

    int start = s_start, cnt = s_cnt;
    const float4* base = (const float4*)seq + (size_t)(b * SS + start) * (DD / 4) + tid;
    float4 acc = make_float4(0.f, 0.f, 0.f, 0.f);
#pragma unroll 4
    for (int w = 0; w < cnt; w++) {
        float a  = s_attn[w];
        float4 v = base[(size_t)w * (DD / 4)];
        acc.x += a * v.x; acc.y += a * v.y; acc.z += a * v.z; acc.w += a * v.w;
    }
    ((float4*)g_att)[(size_t)sp * (DD / 4) + tid] = acc;
}

// ---------------- Kernel 3: FFNN GEMM  g_att[4096,768] @ W[768,100], split-K=2 --
// grid = (64 row-blocks, 2 k-splits), 224 threads (200 active compute threads)
__global__ void k_gemm(const float* __restrict__ W) {
    __shared__ float sA[32][68];    // transposed: sA[kk][row], padded
    __shared__ float sW[32][100];
    int m0     = blockIdx.x * 64;
    int ks     = blockIdx.y;
    int k_base = ks * 384;
    int tid    = threadIdx.x;

    float acc[8][4];
#pragma unroll
    for (int i = 0; i < 8; i++)
#pragma unroll
        for (int j = 0; j < 4; j++) acc[i][j] = 0.f;

    int rg = tid / 25, cg = tid % 25;
    int rr = rg * 8,  cc = cg * 4;

    for (int kc = 0; kc < 384; kc += 32) {
        int k0 = k_base + kc;
        for (int idx = tid; idx < 64 * 32; idx += 224) {
            int r = idx >> 5, kk = idx & 31;
            sA[kk][r] = g_att[(size_t)(m0 + r) * DD + k0 + kk];
        }
        for (int idx = tid; idx < 32 * 100; idx += 224) {
            int kk = idx / 100, c = idx % 100;
            sW[kk][c] = W[(size_t)(k0 + kk) * HH + c];
        }
        __syncthreads();

        if (tid < 200) {
#pragma unroll
            for (int kk = 0; kk < 32; kk++) {
                float4 a0 = *(const float4*)&sA[kk][rr];
                float4 a1 = *(const float4*)&sA[kk][rr + 4];
                float4 w  = *(const float4*)&sW[kk][cc];
                float av[8] = {a0.x, a0.y, a0.z, a0.w, a1.x, a1.y, a1.z, a1.w};
                float wv[4] = {w.x, w.y, w.z, w.w};
#pragma unroll
                for (int i = 0; i < 8; i++)
#pragma unroll
                    for (int j = 0; j < 4; j++) acc[i][j] += av[i] * wv[j];
            }
        }
        __syncthreads();
    }

    if (tid < 200) {
#pragma unroll
        for (int i = 0; i < 8; i++) {
            size_t o = ((size_t)ks * M_TOTAL + m0 + rr + i) * HH + cc;
            float4 v = make_float4(acc[i][0], acc[i][1], acc[i][2], acc[i][3]);
            *(float4*)&g_part[o] = v;
        }
    }
}

// ---------------- Kernel 4: combine split-K partials + bias + tanh -------------
__global__ void k_epi(const float* __restrict__ bias, float* __restrict__ out) {
    int i = blockIdx.x * 256 + threadIdx.x;
    if (i < M_TOTAL * HH) {
        int h = i % HH;
        out[i] = tanhf(g_part[i] + g_part[(size_t)M_TOTAL * HH + i] + bias[h]);
    }
}

extern "C" void kernel_launch(void* const* d_in, const int* in_sizes, int n_in,
                              void* d_out, int out_size) {
    const float*      seq   = (const float*)d_in[0];
    const int*        spans = (const int*)d_in[1];
    const int*        mask  = (const int*)d_in[2];
    const float*      att_w = (const float*)d_in[3];
    const float*      att_b = (const float*)d_in[4];
    const float*      ffn_w = (const float*)d_in[5];
    const float*      ffn_b = (const float*)d_in[6];
    float*            out   = (float*)d_out;

    k_logits<<<(BB * SS) / 8, 256>>>(seq, att_w, att_b);
    k_span<<<M_TOTAL, 192>>>(seq, spans, mask);
    k_gemm<<<dim3(64, 2), 224>>>(ffn_w);
    k_epi<<<(M_TOTAL * HH + 255) / 256, 256>>>(ffn_b, out);
}

// round 3
// speedup vs baseline: 1.5111x; 1.5111x over previous
#include <cuda_runtime.h>

#define BB 8
#define SS 2048
#define DD 768
#define NSP 512
#define MAXW 30
#define HH 100
#define M_TOTAL (BB*NSP)   /* 4096 */

__device__ float g_logits[BB*SS];
__device__ float g_att[(size_t)M_TOTAL*DD];

// ---------------- Kernel 1: attention logits over full sequence ----------------
__global__ void k_logits(const float* __restrict__ seq,
                         const float* __restrict__ att_w,
                         const float* __restrict__ att_b) {
    __shared__ float sw[DD];
    int tid = threadIdx.x;
    for (int i = tid; i < DD; i += blockDim.x) sw[i] = att_w[i];
    __syncthreads();
    int warp = tid >> 5, lane = tid & 31;
    int p = blockIdx.x * 8 + warp;
    const float4* s4 = (const float4*)(seq + (size_t)p * DD);
    const float4* w4 = (const float4*)sw;
    float sum = 0.f;
#pragma unroll
    for (int j = 0; j < 6; j++) {
        float4 a = s4[lane + 32 * j];
        float4 w = w4[lane + 32 * j];
        sum += a.x * w.x + a.y * w.y + a.z * w.z + a.w * w.w;
    }
#pragma unroll
    for (int o = 16; o > 0; o >>= 1) sum += __shfl_xor_sync(0xffffffffu, sum, o);
    if (lane == 0) g_logits[p] = sum + att_b[0];
}

// ---------------- Kernel 2: per-span softmax + weighted sum of token rows ------
__global__ void k_span(const float* __restrict__ seq,
                       const int* __restrict__ spans,
                       const int* __restrict__ mask) {
    __shared__ float s_attn[MAXW];
    __shared__ int   s_start, s_cnt;
    int sp  = blockIdx.x;
    int b   = sp >> 9;
    int tid = threadIdx.x;

    if (tid < 32) {
        int start = spans[sp * 2];
        int cnt   = spans[sp * 2 + 1] - start;        // width 1..30
        float lg = (tid < cnt) ? g_logits[b * SS + start + tid] : -1e30f;
        float mx = lg;
#pragma unroll
        for (int o = 16; o > 0; o >>= 1) mx = fmaxf(mx, __shfl_xor_sync(0xffffffffu, mx, o));
        float ex = (tid < cnt) ? expf(lg - mx) : 0.f;
        float sm = ex;
#pragma unroll
        for (int o = 16; o > 0; o >>= 1) sm += __shfl_xor_sync(0xffffffffu, sm, o);
        float mk = (float)mask[sp];
        if (tid < MAXW) s_attn[tid] = ex / sm * mk;
        if (tid == 0) { s_start = start; s_cnt = cnt; }
    }
    __syncthreads();

    int start = s_start, cnt = s_cnt;
    const float4* base = (const float4*)seq + (size_t)(b * SS + start) * (DD / 4) + tid;
    float4 acc = make_float4(0.f, 0.f, 0.f, 0.f);
#pragma unroll 4
    for (int w = 0; w < cnt; w++) {
        float a  = s_attn[w];
        float4 v = base[(size_t)w * (DD / 4)];
        acc.x += a * v.x; acc.y += a * v.y; acc.z += a * v.z; acc.w += a * v.w;
    }
    ((float4*)g_att)[(size_t)sp * (DD / 4) + tid] = acc;
}

// ---------------- Kernel 3: fused GEMM + bias + tanh ---------------------------
// grid = 128 (M-tile 32), block = 224 (200 compute threads, 4x4 register tiles)
// register-prefetch double buffering of the 32-wide K chunks.
#define KC 32
#define NA_F4 ((32*KC)/4)    /* 256 A float4 per chunk  */
#define NW_F4 ((KC*HH)/4)    /* 800 W float4 per chunk  */

__global__ void __launch_bounds__(224) k_gemm(const float* __restrict__ W,
                                              const float* __restrict__ bias,
                                              float* __restrict__ out) {
    __shared__ float sA[KC][36];     // [kk][row]
    __shared__ float sW[KC][100];
    __shared__ float sB[HH];

    int m0  = blockIdx.x * 32;
    int tid = threadIdx.x;

    if (tid < HH) sB[tid] = bias[tid];

    // per-thread fixed load slots
    int ai0 = tid, ai1 = tid + 224;                 // A f4 slots (ai1 may be >=256)
    int wi0 = tid, wi1 = tid + 224, wi2 = tid + 448, wi3 = tid + 672;

    float4 ra0, ra1, rw0, rw1, rw2, rw3;

    const float4* A4 = (const float4*)g_att;
    const float4* W4 = (const float4*)W;

    // prefetch chunk 0
    {
        int k0 = 0;
        if (ai0 < NA_F4) { int r = ai0 >> 3, kf = ai0 & 7; ra0 = A4[(size_t)(m0 + r) * (DD/4) + (k0>>2) + kf]; }
        if (ai1 < NA_F4) { int r = ai1 >> 3, kf = ai1 & 7; ra1 = A4[(size_t)(m0 + r) * (DD/4) + (k0>>2) + kf]; }
        if (wi0 < NW_F4) { int kk = wi0 / 25, c = wi0 % 25; rw0 = W4[(size_t)(k0 + kk) * (HH/4) + c]; }
        if (wi1 < NW_F4) { int kk = wi1 / 25, c = wi1 % 25; rw1 = W4[(size_t)(k0 + kk) * (HH/4) + c]; }
        if (wi2 < NW_F4) { int kk = wi2 / 25, c = wi2 % 25; rw2 = W4[(size_t)(k0 + kk) * (HH/4) + c]; }
        if (wi3 < NW_F4) { int kk = wi3 / 25, c = wi3 % 25; rw3 = W4[(size_t)(k0 + kk) * (HH/4) + c]; }
    }

    float acc[4][4];
#pragma unroll
    for (int i = 0; i < 4; i++)
#pragma unroll
        for (int j = 0; j < 4; j++) acc[i][j] = 0.f;

    int rg = tid / 25, cg = tid % 25;   // rg 0..8 (rg<8 active)
    int rr = rg * 4,  cc = cg * 4;
    bool active = (tid < 200);

    for (int kc = 0; kc < DD; kc += KC) {
        // store prefetched regs -> smem
        if (ai0 < NA_F4) { int r = ai0 >> 3, kf = (ai0 & 7) * 4;
            sA[kf+0][r] = ra0.x; sA[kf+1][r] = ra0.y; sA[kf+2][r] = ra0.z; sA[kf+3][r] = ra0.w; }
        if (ai1 < NA_F4) { int r = ai1 >> 3, kf = (ai1 & 7) * 4;
            sA[kf+0][r] = ra1.x; sA[kf+1][r] = ra1.y; sA[kf+2][r] = ra1.z; sA[kf+3][r] = ra1.w; }
        if (wi0 < NW_F4) { int kk = wi0 / 25, c = (wi0 % 25) * 4; *(float4*)&sW[kk][c] = rw0; }
        if (wi1 < NW_F4) { int kk = wi1 / 25, c = (wi1 % 25) * 4; *(float4*)&sW[kk][c] = rw1; }
        if (wi2 < NW_F4) { int kk = wi2 / 25, c = (wi2 % 25) * 4; *(float4*)&sW[kk][c] = rw2; }
        if (wi3 < NW_F4) { int kk = wi3 / 25, c = (wi3 % 25) * 4; *(float4*)&sW[kk][c] = rw3; }
        __syncthreads();

        // prefetch next chunk
        int kn = kc + KC;
        if (kn < DD) {
            if (ai0 < NA_F4) { int r = ai0 >> 3, kf = ai0 & 7; ra0 = A4[(size_t)(m0 + r) * (DD/4) + (kn>>2) + kf]; }
            if (ai1 < NA_F4) { int r = ai1 >> 3, kf = ai1 & 7; ra1 = A4[(size_t)(m0 + r) * (DD/4) + (kn>>2) + kf]; }
            if (wi0 < NW_F4) { int kk = wi0 / 25, c = wi0 % 25; rw0 = W4[(size_t)(kn + kk) * (HH/4) + c]; }
            if (wi1 < NW_F4) { int kk = wi1 / 25, c = wi1 % 25; rw1 = W4[(size_t)(kn + kk) * (HH/4) + c]; }
            if (wi2 < NW_F4) { int kk = wi2 / 25, c = wi2 % 25; rw2 = W4[(size_t)(kn + kk) * (HH/4) + c]; }
            if (wi3 < NW_F4) { int kk = wi3 / 25, c = wi3 % 25; rw3 = W4[(size_t)(kn + kk) * (HH/4) + c]; }
        }

        if (active) {
#pragma unroll
            for (int kk = 0; kk < KC; kk++) {
                float4 a = *(const float4*)&sA[kk][rr];
                float4 w = *(const float4*)&sW[kk][cc];
                float av[4] = {a.x, a.y, a.z, a.w};
                float wv[4] = {w.x, w.y, w.z, w.w};
#pragma unroll
                for (int i = 0; i < 4; i++)
#pragma unroll
                    for (int j = 0; j < 4; j++) acc[i][j] += av[i] * wv[j];
            }
        }
        __syncthreads();
    }

    if (active) {
#pragma unroll
        for (int i = 0; i < 4; i++) {
            float4 v;
            v.x = tanhf(acc[i][0] + sB[cc + 0]);
            v.y = tanhf(acc[i][1] + sB[cc + 1]);
            v.z = tanhf(acc[i][2] + sB[cc + 2]);
            v.w = tanhf(acc[i][3] + sB[cc + 3]);
            *(float4*)&out[(size_t)(m0 + rr + i) * HH + cc] = v;
        }
    }
}

extern "C" void kernel_launch(void* const* d_in, const int* in_sizes, int n_in,
                              void* d_out, int out_size) {
    const float* seq   = (const float*)d_in[0];
    const int*   spans = (const int*)d_in[1];
    const int*   mask  = (const int*)d_in[2];
    const float* att_w = (const float*)d_in[3];
    const float* att_b = (const float*)d_in[4];
    const float* ffn_w = (const float*)d_in[5];
    const float* ffn_b = (const float*)d_in[6];
    float*       out   = (float*)d_out;

    k_logits<<<(BB * SS) / 8, 256>>>(seq, att_w, att_b);
    k_span<<<M_TOTAL, 192>>>(seq, spans, mask);
    k_gemm<<<128, 224>>>(ffn_w, ffn_b, out);
}

// round 4
// speedup vs baseline: 1.5592x; 1.0318x over previous
#include <cuda_runtime.h>

#define BB 8
#define SS 2048
#define DD 768
#define NSP 512
#define MAXW 30
#define HH 100
#define M_TOTAL (BB*NSP)   /* 4096 */

__device__ float g_logits[BB*SS];
__device__ float g_att[(size_t)M_TOTAL*DD];

__device__ __forceinline__ unsigned long long f32x2_pack(float x, float y) {
    unsigned long long r;
    asm("mov.b64 %0, {%1, %2};" : "=l"(r) : "r"(__float_as_uint(x)), "r"(__float_as_uint(y)));
    return r;
}
__device__ __forceinline__ void f32x2_fma(unsigned long long& acc,
                                          unsigned long long a, unsigned long long b) {
    asm("fma.rn.f32x2 %0, %1, %2, %0;" : "+l"(acc) : "l"(a), "l"(b));
}
__device__ __forceinline__ float2 f32x2_unpack(unsigned long long v) {
    unsigned int lo, hi;
    asm("mov.b64 {%0, %1}, %2;" : "=r"(lo), "=r"(hi) : "l"(v));
    return make_float2(__uint_as_float(lo), __uint_as_float(hi));
}

// ---------------- Kernel 1: attention logits, 2 rows per warp ------------------
// grid = 1024, block = 256 (8 warps x 2 rows = 16 rows/block)
__global__ void __launch_bounds__(256) k_logits(const float* __restrict__ seq,
                                                const float* __restrict__ att_w,
                                                const float* __restrict__ att_b) {
    __shared__ float sw[DD];
    int tid = threadIdx.x;
    for (int i = tid; i < DD; i += 256) sw[i] = att_w[i];
    __syncthreads();
    int warp = tid >> 5, lane = tid & 31;

    float4 wreg[6];
    const float4* w4 = (const float4*)sw;
#pragma unroll
    for (int j = 0; j < 6; j++) wreg[j] = w4[lane + 32 * j];

    int p0 = (blockIdx.x * 8 + warp) * 2;
    const float4* r0 = (const float4*)(seq + (size_t)p0 * DD);
    const float4* r1 = (const float4*)(seq + (size_t)(p0 + 1) * DD);

    float s0 = 0.f, s1 = 0.f;
#pragma unroll
    for (int j = 0; j < 6; j++) {
        float4 x = r0[lane + 32 * j];
        float4 y = r1[lane + 32 * j];
        s0 += x.x * wreg[j].x + x.y * wreg[j].y + x.z * wreg[j].z + x.w * wreg[j].w;
        s1 += y.x * wreg[j].x + y.y * wreg[j].y + y.z * wreg[j].z + y.w * wreg[j].w;
    }
#pragma unroll
    for (int o = 16; o > 0; o >>= 1) {
        s0 += __shfl_xor_sync(0xffffffffu, s0, o);
        s1 += __shfl_xor_sync(0xffffffffu, s1, o);
    }
    if (lane == 0) {
        float b = att_b[0];
        g_logits[p0]     = s0 + b;
        g_logits[p0 + 1] = s1 + b;
    }
}

// ---------------- Kernel 2: per-span softmax + weighted sum of token rows ------
__global__ void k_span(const float* __restrict__ seq,
                       const int* __restrict__ spans,
                       const int* __restrict__ mask) {
    __shared__ float s_attn[MAXW];
    __shared__ int   s_start, s_cnt;
    int sp  = blockIdx.x;
    int b   = sp >> 9;
    int tid = threadIdx.x;

    if (tid < 32) {
        int start = spans[sp * 2];
        int cnt   = spans[sp * 2 + 1] - start;        // width 1..30
        float lg = (tid < cnt) ? g_logits[b * SS + start + tid] : -1e30f;
        float mx = lg;
#pragma unroll
        for (int o = 16; o > 0; o >>= 1) mx = fmaxf(mx, __shfl_xor_sync(0xffffffffu, mx, o));
        float ex = (tid < cnt) ? expf(lg - mx) : 0.f;
        float sm = ex;
#pragma unroll
        for (int o = 16; o > 0; o >>= 1) sm += __shfl_xor_sync(0xffffffffu, sm, o);
        float mk = (float)mask[sp];
        if (tid < MAXW) s_attn[tid] = ex / sm * mk;
        if (tid == 0) { s_start = start; s_cnt = cnt; }
    }
    __syncthreads();

    int start = s_start, cnt = s_cnt;
    const float4* base = (const float4*)seq + (size_t)(b * SS + start) * (DD / 4) + tid;
    float4 acc = make_float4(0.f, 0.f, 0.f, 0.f);
#pragma unroll 4
    for (int w = 0; w < cnt; w++) {
        float a  = s_attn[w];
        float4 v = base[(size_t)w * (DD / 4)];
        acc.x += a * v.x; acc.y += a * v.y; acc.z += a * v.z; acc.w += a * v.w;
    }
    ((float4*)g_att)[(size_t)sp * (DD / 4) + tid] = acc;
}

// ---------------- Kernel 3: fused GEMM + bias + tanh (f32x2 packed FMA) --------
#define KC 32
#define NA_F4 ((32*KC)/4)    /* 256 A float4 per chunk  */
#define NW_F4 ((KC*HH)/4)    /* 800 W float4 per chunk  */

__global__ void __launch_bounds__(224) k_gemm(const float* __restrict__ W,
                                              const float* __restrict__ bias,
                                              float* __restrict__ out) {
    __shared__ float sA[KC][36];     // [kk][row]
    __shared__ float sW[KC][100];
    __shared__ float sB[HH];

    int m0  = blockIdx.x * 32;
    int tid = threadIdx.x;

    if (tid < HH) sB[tid] = bias[tid];

    int ai0 = tid, ai1 = tid + 224;
    int wi0 = tid, wi1 = tid + 224, wi2 = tid + 448, wi3 = tid + 672;

    float4 ra0, ra1, rw0, rw1, rw2, rw3;

    const float4* A4 = (const float4*)g_att;
    const float4* W4 = (const float4*)W;

    {
        int k0 = 0;
        if (ai0 < NA_F4) { int r = ai0 >> 3, kf = ai0 & 7; ra0 = A4[(size_t)(m0 + r) * (DD/4) + (k0>>2) + kf]; }
        if (ai1 < NA_F4) { int r = ai1 >> 3, kf = ai1 & 7; ra1 = A4[(size_t)(m0 + r) * (DD/4) + (k0>>2) + kf]; }
        if (wi0 < NW_F4) { int kk = wi0 / 25, c = wi0 % 25; rw0 = W4[(size_t)(k0 + kk) * (HH/4) + c]; }
        if (wi1 < NW_F4) { int kk = wi1 / 25, c = wi1 % 25; rw1 = W4[(size_t)(k0 + kk) * (HH/4) + c]; }
        if (wi2 < NW_F4) { int kk = wi2 / 25, c = wi2 % 25; rw2 = W4[(size_t)(k0 + kk) * (HH/4) + c]; }
        if (wi3 < NW_F4) { int kk = wi3 / 25, c = wi3 % 25; rw3 = W4[(size_t)(k0 + kk) * (HH/4) + c]; }
    }

    unsigned long long accP[4][2];   // [i][jpair], each = (acc[i][2jp], acc[i][2jp+1])
#pragma unroll
    for (int i = 0; i < 4; i++) { accP[i][0] = 0ull; accP[i][1] = 0ull; }

    int rg = tid / 25, cg = tid % 25;
    int rr = rg * 4,  cc = cg * 4;
    bool active = (tid < 200);

    for (int kc = 0; kc < DD; kc += KC) {
        if (ai0 < NA_F4) { int r = ai0 >> 3, kf = (ai0 & 7) * 4;
            sA[kf+0][r] = ra0.x; sA[kf+1][r] = ra0.y; sA[kf+2][r] = ra0.z; sA[kf+3][r] = ra0.w; }
        if (ai1 < NA_F4) { int r = ai1 >> 3, kf = (ai1 & 7) * 4;
            sA[kf+0][r] = ra1.x; sA[kf+1][r] = ra1.y; sA[kf+2][r] = ra1.z; sA[kf+3][r] = ra1.w; }
        if (wi0 < NW_F4) { int kk = wi0 / 25, c = (wi0 % 25) * 4; *(float4*)&sW[kk][c] = rw0; }
        if (wi1 < NW_F4) { int kk = wi1 / 25, c = (wi1 % 25) * 4; *(float4*)&sW[kk][c] = rw1; }
        if (wi2 < NW_F4) { int kk = wi2 / 25, c = (wi2 % 25) * 4; *(float4*)&sW[kk][c] = rw2; }
        if (wi3 < NW_F4) { int kk = wi3 / 25, c = (wi3 % 25) * 4; *(float4*)&sW[kk][c] = rw3; }
        __syncthreads();

        int kn = kc + KC;
        if (kn < DD) {
            if (ai0 < NA_F4) { int r = ai0 >> 3, kf = ai0 & 7; ra0 = A4[(size_t)(m0 + r) * (DD/4) + (kn>>2) + kf]; }
            if (ai1 < NA_F4) { int r = ai1 >> 3, kf = ai1 & 7; ra1 = A4[(size_t)(m0 + r) * (DD/4) + (kn>>2) + kf]; }
            if (wi0 < NW_F4) { int kk = wi0 / 25, c = wi0 % 25; rw0 = W4[(size_t)(kn + kk) * (HH/4) + c]; }
            if (wi1 < NW_F4) { int kk = wi1 / 25, c = wi1 % 25; rw1 = W4[(size_t)(kn + kk) * (HH/4) + c]; }
            if (wi2 < NW_F4) { int kk = wi2 / 25, c = wi2 % 25; rw2 = W4[(size_t)(kn + kk) * (HH/4) + c]; }
            if (wi3 < NW_F4) { int kk = wi3 / 25, c = wi3 % 25; rw3 = W4[(size_t)(kn + kk) * (HH/4) + c]; }
        }

        if (active) {
#pragma unroll
            for (int kk = 0; kk < KC; kk++) {
                float4 a = *(const float4*)&sA[kk][rr];
                float4 w = *(const float4*)&sW[kk][cc];
                unsigned long long w01 = f32x2_pack(w.x, w.y);
                unsigned long long w23 = f32x2_pack(w.z, w.w);
                float av[4] = {a.x, a.y, a.z, a.w};
#pragma unroll
                for (int i = 0; i < 4; i++) {
                    unsigned long long ad = f32x2_pack(av[i], av[i]);
                    f32x2_fma(accP[i][0], ad, w01);
                    f32x2_fma(accP[i][1], ad, w23);
                }
            }
        }
        __syncthreads();
    }

    if (active) {
#pragma unroll
        for (int i = 0; i < 4; i++) {
            float2 p0 = f32x2_unpack(accP[i][0]);
            float2 p1 = f32x2_unpack(accP[i][1]);
            float4 v;
            v.x = tanhf(p0.x + sB[cc + 0]);
            v.y = tanhf(p0.y + sB[cc + 1]);
            v.z = tanhf(p1.x + sB[cc + 2]);
            v.w = tanhf(p1.y + sB[cc + 3]);
            *(float4*)&out[(size_t)(m0 + rr + i) * HH + cc] = v;
        }
    }
}

extern "C" void kernel_launch(void* const* d_in, const int* in_sizes, int n_in,
                              void* d_out, int out_size) {
    const float* seq   = (const float*)d_in[0];
    const int*   spans = (const int*)d_in[1];
    const int*   mask  = (const int*)d_in[2];
    const float* att_w = (const float*)d_in[3];
    const float* att_b = (const float*)d_in[4];
    const float* ffn_w = (const float*)d_in[5];
    const float* ffn_b = (const float*)d_in[6];
    float*       out   = (float*)d_out;

    k_logits<<<(BB * SS) / 16, 256>>>(seq, att_w, att_b);
    k_span<<<M_TOTAL, 192>>>(seq, spans, mask);
    k_gemm<<<128, 224>>>(ffn_w, ffn_b, out);
}